// round 3
// baseline (speedup 1.0000x reference)
#include <cuda_runtime.h>
#include <math.h>

#define BATCH 16384
#define KNN 5

// ---------------- scratch (static device arrays; no allocation) ----------------
__device__ float g_h1[BATCH * 20 * 300];   // layer1 output
__device__ float g_h2[BATCH * 20 * 100];   // layer2 output
__device__ float g_C[3 * 400];             // kNN edge counts per layer
__device__ float g_M[3 * 400];             // aggregation matrices

// ---------------- tiny kernels ----------------
__global__ void zero_counts_kernel(float* C) {
    int t = blockIdx.x * blockDim.x + threadIdx.x;
    if (t < 1200) C[t] = 0.f;
}

__global__ void build_M_kernel(const float* __restrict__ C, float* __restrict__ M) {
    __shared__ float dinv[20];
    int t = threadIdx.x;
    if (t < 20) {
        float s = 1.f;
#pragma unroll
        for (int u = 0; u < 20; u++) s += C[t * 20 + u];
        dinv[t] = 1.f / sqrtf(s);
    }
    __syncthreads();
    for (int i = t; i < 400; i += blockDim.x) {
        int v = i / 20, u = i % 20;
        float m = dinv[v] * C[i] * dinv[u];
        if (v == u) m += dinv[v] * dinv[v];
        M[i] = m;
    }
}

// ---------------- block-local kNN + count accumulation ----------------
// sh: [NS*20][DIMP] feature tile in smem. Emulates jax top_k(-d2, k+1)[1:]
// (self excluded; ties -> lower index, matched by strict < with ascending u).
template<int NS, int DIM, int DIMP>
__device__ void knn_accumulate(const float* __restrict__ sh,
                               float* __restrict__ sdq, float* __restrict__ sd2,
                               float* __restrict__ sC, float* __restrict__ gC,
                               int tid) {
    constexpr int ROWS = NS * 20;
    for (int i = tid; i < 400; i += 256) sC[i] = 0.f;
    for (int t = tid; t < ROWS; t += 256) {
        const float* hp = sh + t * DIMP;
        float s = 0.f;
        for (int d = 0; d < DIM; d++) { float h = hp[d]; s += h * h; }
        sdq[t] = s;
    }
    __syncthreads();
    for (int t = tid; t < NS * 190; t += 256) {
        int s = t / 190, rem = t % 190;
        int i = 0;
        while (rem >= 19 - i) { rem -= 19 - i; i++; }
        int j = i + 1 + rem;
        const float* ha = sh + (s * 20 + i) * DIMP;
        const float* hb = sh + (s * 20 + j) * DIMP;
        float dot = 0.f;
        for (int d = 0; d < DIM; d++) dot += ha[d] * hb[d];
        float d2 = sdq[s * 20 + i] + sdq[s * 20 + j] - 2.f * dot;
        sd2[s * 400 + i * 20 + j] = d2;
        sd2[s * 400 + j * 20 + i] = d2;
    }
    __syncthreads();
    for (int t = tid; t < ROWS; t += 256) {
        int s = t / 20, v = t % 20;
        const float* row = sd2 + s * 400 + v * 20;
        float bv[KNN]; int bi[KNN];
#pragma unroll
        for (int k = 0; k < KNN; k++) { bv[k] = 3.4e38f; bi[k] = 99; }
        for (int u = 0; u < 20; u++) {
            if (u == v) continue;
            float d = row[u];
            if (d < bv[KNN - 1]) {
                bv[KNN - 1] = d; bi[KNN - 1] = u;
#pragma unroll
                for (int k = KNN - 1; k > 0; k--) {
                    if (bv[k] < bv[k - 1]) {
                        float tv = bv[k]; bv[k] = bv[k - 1]; bv[k - 1] = tv;
                        int ti = bi[k]; bi[k] = bi[k - 1]; bi[k - 1] = ti;
                    }
                }
            }
        }
#pragma unroll
        for (int k = 0; k < KNN; k++)
            atomicAdd(&sC[bi[k] * 20 + v], 1.f);   // C[nbr][src]
    }
    __syncthreads();
    for (int i = tid; i < 400; i += 256) {
        float c = sC[i];
        if (c != 0.f) atomicAdd(&gC[i], c);
    }
}

// ---------------- kNN on raw x (layer-1 counts) ----------------
template<int NS>
__global__ __launch_bounds__(256) void knn0_kernel(const float* __restrict__ x,
                                                   float* __restrict__ gC) {
    constexpr int DIM = 128, DIMP = 129, ROWS = NS * 20;
    extern __shared__ float sm[];
    float* sh  = sm;
    float* sdq = sh + ROWS * DIMP;
    float* sd2 = sdq + ROWS;
    float* sC  = sd2 + NS * 400;
    int tid = threadIdx.x;
    size_t samp0 = (size_t)blockIdx.x * NS;
    const float* gx = x + samp0 * 20 * DIM;
    for (int idx = tid; idx < ROWS * DIM; idx += 256) {
        int r = idx / DIM, d = idx - r * DIM;
        sh[r * DIMP + d] = gx[idx];
    }
    __syncthreads();
    knn_accumulate<NS, DIM, DIMP>(sh, sdq, sd2, sC, gC, tid);
}

// ---------------- fused GCN layer: z = h@W^T ; h' = relu(M z + b) ; knn(h') ----------------
template<int DIN, int DOUT, int NS, bool DO_KNN>
__global__ __launch_bounds__(256) void layer_kernel(
    const float* __restrict__ hin, const float* __restrict__ W,
    const float* __restrict__ bias, const float* __restrict__ Mptr,
    float* __restrict__ hout, float* __restrict__ Cnext) {
    constexpr int DINP = DIN + 1;
    constexpr int DOUTP = DOUT | 1;
    constexpr int ROWS = NS * 20;
    constexpr int WCH = 64, CPT = 4;
    extern __shared__ float sm[];
    float* sM  = sm;                    // 400
    float* sb  = sM + 400;              // DOUT
    float* sh  = sb + DOUT;             // ROWS*DINP
    float* sz  = sh + ROWS * DINP;      // ROWS*DOUTP
    float* sW  = sz + ROWS * DOUTP;     // WCH*DINP
    float* sdq = sW + WCH * DINP;       // ROWS
    float* sd2 = sdq + ROWS;            // NS*400
    float* sC  = sd2 + NS * 400;        // 400

    int tid = threadIdx.x;
    size_t samp0 = (size_t)blockIdx.x * NS;

    for (int i = tid; i < 400; i += 256) sM[i] = Mptr[i];
    for (int i = tid; i < DOUT; i += 256) sb[i] = bias[i];
    const float* gh = hin + samp0 * 20 * DIN;
    for (int idx = tid; idx < ROWS * DIN; idx += 256) {
        int r = idx / DIN, d = idx - r * DIN;
        sh[r * DINP + d] = gh[idx];
    }
    __syncthreads();

    int lane = tid & 31, wid = tid >> 5;
    float Mr[20];
    {
        int v = lane < 20 ? lane : 0;
#pragma unroll
        for (int u = 0; u < 20; u++) Mr[u] = sM[v * 20 + u];
    }

    // GEMM: sz[r][o] = sum_d sh[r][d] * W[o][d]
    int ty = tid >> 4, tx = tid & 15;
    for (int cb = 0; cb < DOUT; cb += WCH) {
        __syncthreads();
        for (int idx = tid; idx < WCH * DIN; idx += 256) {
            int c = idx / DIN, d = idx - c * DIN;
            int gc = cb + c;
            sW[c * DINP + d] = (gc < DOUT) ? W[(size_t)gc * DIN + d] : 0.f;
        }
        __syncthreads();
        float acc[5][CPT];
#pragma unroll
        for (int i = 0; i < 5; i++)
#pragma unroll
            for (int k = 0; k < CPT; k++) acc[i][k] = 0.f;
        const float* shp = sh + (ty * 5) * DINP;
        const float* swp = sW + (tx * CPT) * DINP;
        for (int d = 0; d < DIN; d++) {
            float a0 = shp[d];
            float a1 = shp[DINP + d];
            float a2 = shp[2 * DINP + d];
            float a3 = shp[3 * DINP + d];
            float a4 = shp[4 * DINP + d];
#pragma unroll
            for (int k = 0; k < CPT; k++) {
                float w = swp[k * DINP + d];
                acc[0][k] += a0 * w;
                acc[1][k] += a1 * w;
                acc[2][k] += a2 * w;
                acc[3][k] += a3 * w;
                acc[4][k] += a4 * w;
            }
        }
#pragma unroll
        for (int k = 0; k < CPT; k++) {
            int gc = cb + tx * CPT + k;
            if (gc < DOUT) {
#pragma unroll
                for (int i = 0; i < 5; i++)
                    sz[(ty * 5 + i) * DOUTP + gc] = acc[i][k];
            }
        }
    }
    __syncthreads();

    // in-place h' = relu(M z + b): one warp owns each (sample, out-col)
    for (int col = wid; col < NS * DOUT; col += 8) {
        int s = col / DOUT, o = col - s * DOUT;
        float* zc = sz + (s * 20) * DOUTP + o;
        float a = 0.f;
#pragma unroll
        for (int u = 0; u < 20; u++) a += Mr[u] * zc[u * DOUTP];
        float h = fmaxf(a + sb[o], 0.f);
        __syncwarp();
        if (lane < 20) zc[lane * DOUTP] = h;
        __syncwarp();
    }
    __syncthreads();

    float* go = hout + samp0 * 20 * DOUT;
    for (int idx = tid; idx < ROWS * DOUT; idx += 256) {
        int r = idx / DOUT, o = idx - r * DOUT;
        go[idx] = sz[r * DOUTP + o];
    }

    if (DO_KNN)
        knn_accumulate<NS, DOUT, DOUTP>(sz, sdq, sd2, sC, Cnext, tid);
}

// ---------------- layer3 + flatten + FC head + softmax ----------------
__global__ __launch_bounds__(256) void final_kernel(
    const float* __restrict__ hin, const float* __restrict__ W3, const float* __restrict__ b3,
    const float* __restrict__ Mptr, const float* __restrict__ W4, const float* __restrict__ b4,
    const float* __restrict__ W5, const float* __restrict__ b5, float* __restrict__ out) {
    constexpr int DIN = 100, DINP = 101, DOUT = 50, DOUTP = 51;
    constexpr int NS = 8, ROWS = 160, WCH = 64, CPT = 4;
    extern __shared__ float sm[];
    float* sM  = sm;                 // 400
    float* sb3 = sM + 400;           // 64 (padded)
    float* sh  = sb3 + 64;           // 160*101
    float* sz  = sh + ROWS * DINP;   // 160*51
    float* sW  = sz + ROWS * DOUTP;  // 64*101
    float* sW4 = sW + WCH * DINP;    // 16*1000
    float* sh4 = sW4 + 16000;        // 8*100
    float* ph  = sh4 + NS * 100;     // 256
    float* sW5 = ph + 256;           // 300
    float* sb5 = sW5 + 300;          // 4
    float* sb4 = sb5 + 4;            // 100

    int tid = threadIdx.x;
    size_t samp0 = (size_t)blockIdx.x * NS;

    for (int i = tid; i < 400; i += 256) sM[i] = Mptr[i];
    for (int i = tid; i < DOUT; i += 256) sb3[i] = b3[i];
    for (int i = tid; i < 300; i += 256) sW5[i] = W5[i];
    for (int i = tid; i < 100; i += 256) sb4[i] = b4[i];
    if (tid < 3) sb5[tid] = b5[tid];
    const float* gh = hin + samp0 * 20 * DIN;
    for (int idx = tid; idx < ROWS * DIN; idx += 256) {
        int r = idx / DIN, d = idx - r * DIN;
        sh[r * DINP + d] = gh[idx];
    }
    // W3 chunk (single, zero-padded to WCH)
    for (int idx = tid; idx < WCH * DIN; idx += 256) {
        int c = idx / DIN, d = idx - c * DIN;
        sW[c * DINP + d] = (c < DOUT) ? W3[c * DIN + d] : 0.f;
    }
    __syncthreads();

    int lane = tid & 31, wid = tid >> 5;
    float Mr[20];
    {
        int v = lane < 20 ? lane : 0;
#pragma unroll
        for (int u = 0; u < 20; u++) Mr[u] = sM[v * 20 + u];
    }

    // GEMM z = h @ W3^T : 160 rows, 10 rows per ty
    int ty = tid >> 4, tx = tid & 15;
    {
        float acc[10][CPT];
#pragma unroll
        for (int i = 0; i < 10; i++)
#pragma unroll
            for (int k = 0; k < CPT; k++) acc[i][k] = 0.f;
        const float* shp = sh + (ty * 10) * DINP;
        const float* swp = sW + (tx * CPT) * DINP;
        for (int d = 0; d < DIN; d++) {
            float a[10];
#pragma unroll
            for (int i = 0; i < 10; i++) a[i] = shp[i * DINP + d];
#pragma unroll
            for (int k = 0; k < CPT; k++) {
                float w = swp[k * DINP + d];
#pragma unroll
                for (int i = 0; i < 10; i++) acc[i][k] += a[i] * w;
            }
        }
#pragma unroll
        for (int k = 0; k < CPT; k++) {
            int gc = tx * CPT + k;
            if (gc < DOUT) {
#pragma unroll
                for (int i = 0; i < 10; i++)
                    sz[(ty * 10 + i) * DOUTP + gc] = acc[i][k];
            }
        }
    }
    __syncthreads();

    // h3 = relu(M z + b3) in place
    for (int col = wid; col < NS * DOUT; col += 8) {
        int s = col / DOUT, o = col - s * DOUT;
        float* zc = sz + (s * 20) * DOUTP + o;
        float a = 0.f;
#pragma unroll
        for (int u = 0; u < 20; u++) a += Mr[u] * zc[u * DOUTP];
        float h = fmaxf(a + sb3[o], 0.f);
        __syncwarp();
        if (lane < 20) zc[lane * DOUTP] = h;
        __syncwarp();
    }
    __syncthreads();

    // head: h4 = relu(flat @ W4^T + b4), W4 streamed in 16-row smem chunks.
    // NOTE: 100 rows = 6 full chunks of 16 + final partial chunk of 4.
    // All accesses beyond row 100 are guarded (load zero-pads, write skips).
    for (int jc = 0; jc < 100; jc += 16) {
        __syncthreads();
        for (int idx = tid; idx < 16000; idx += 256) {
            int r = jc + idx / 1000;
            sW4[idx] = (r < 100) ? W4[(size_t)jc * 1000 + idx] : 0.f;
        }
        __syncthreads();
        int task = tid & 127;   // (s, jl) pair
        int half = tid >> 7;    // split n-dim in two
        int s = task >> 4, jl = task & 15;
        const float* zrow = sz + (s * 20) * DOUTP;
        const float* wrow = sW4 + jl * 1000;
        float p = 0.f;
        int v0 = half * 10;
        for (int v = v0; v < v0 + 10; v++) {
            const float* zp = zrow + v * DOUTP;
            const float* wp = wrow + v * 50;
#pragma unroll 10
            for (int f = 0; f < 50; f++) p += zp[f] * wp[f];
        }
        ph[tid] = p;
        __syncthreads();
        if (tid < 128) {
            int s2 = tid >> 4, jl2 = tid & 15;
            if (jc + jl2 < 100) {
                float hv = ph[tid] + ph[tid + 128] + sb4[jc + jl2];
                sh4[s2 * 100 + jc + jl2] = fmaxf(hv, 0.f);
            }
        }
    }
    __syncthreads();

    // logits + softmax
    if (tid < NS) {
        const float* hp = sh4 + tid * 100;
        float l[3];
#pragma unroll
        for (int c = 0; c < 3; c++) {
            float a = sb5[c];
            for (int j = 0; j < 100; j++) a += hp[j] * sW5[c * 100 + j];
            l[c] = a;
        }
        float mx = fmaxf(l[0], fmaxf(l[1], l[2]));
        float e0 = expf(l[0] - mx), e1 = expf(l[1] - mx), e2 = expf(l[2] - mx);
        float inv = 1.f / (e0 + e1 + e2);
        size_t ob = (samp0 + (size_t)tid) * 3;
        out[ob + 0] = e0 * inv;
        out[ob + 1] = e1 * inv;
        out[ob + 2] = e2 * inv;
    }
}

// ---------------- host ----------------
static size_t layer_smem_bytes(int DIN, int DOUT, int NS, int WCH) {
    int DINP = DIN + 1, DOUTP = DOUT | 1, ROWS = NS * 20;
    return sizeof(float) * (size_t)(400 + DOUT + ROWS * DINP + ROWS * DOUTP +
                                    WCH * DINP + ROWS + NS * 400 + 400);
}

extern "C" void kernel_launch(void* const* d_in, const int* in_sizes, int n_in,
                              void* d_out, int out_size) {
    // ---- robust, size-driven input resolution ----
    // Expected element counts:
    //   x: 41943040, W1: 38400, b1: 300, W2: 30000, b2: 100,
    //   W3: 5000, b3: 50, W4: 100000, b4: 100, W5: 300, b5: 3
    const float *x = 0, *W1 = 0, *b1 = 0, *W2 = 0, *b2 = 0, *W3 = 0, *b3 = 0,
                *W4 = 0, *b4 = 0, *W5 = 0, *b5 = 0;
    int idx_x = -1;
    for (int i = 0; i < n_in; i++) if (in_sizes[i] == 41943040) { idx_x = i; break; }
    if (idx_x == 0 || idx_x < 0) {
        // insertion order: x, W1, b1, W2, b2, W3, b3, W4, b4, W5, b5
        x  = (const float*)d_in[0];
        W1 = (const float*)d_in[1];  b1 = (const float*)d_in[2];
        W2 = (const float*)d_in[3];  b2 = (const float*)d_in[4];
        W3 = (const float*)d_in[5];  b3 = (const float*)d_in[6];
        W4 = (const float*)d_in[7];  b4 = (const float*)d_in[8];
        W5 = (const float*)d_in[9];  b5 = (const float*)d_in[10];
    } else {
        // resolve uniques by size; collisions by order (first 300 = earlier name)
        int i300_a = -1, i300_b = -1, i100_a = -1, i100_b = -1;
        for (int i = 0; i < n_in; i++) {
            int s = in_sizes[i];
            if (s == 38400)  W1 = (const float*)d_in[i];
            else if (s == 30000) W2 = (const float*)d_in[i];
            else if (s == 5000)  W3 = (const float*)d_in[i];
            else if (s == 100000) W4 = (const float*)d_in[i];
            else if (s == 50)    b3 = (const float*)d_in[i];
            else if (s == 3)     b5 = (const float*)d_in[i];
            else if (s == 41943040) x = (const float*)d_in[i];
            else if (s == 300) { if (i300_a < 0) i300_a = i; else i300_b = i; }
            else if (s == 100) { if (i100_a < 0) i100_a = i; else i100_b = i; }
        }
        // alphabetical (ASCII): W5 precedes b1; b2 precedes b4
        W5 = (const float*)d_in[i300_a];  b1 = (const float*)d_in[i300_b];
        b2 = (const float*)d_in[i100_a];  b4 = (const float*)d_in[i100_b];
    }
    float* out = (float*)d_out;

    float *pC = nullptr, *pM = nullptr, *ph1 = nullptr, *ph2 = nullptr;
    cudaGetSymbolAddress((void**)&pC, g_C);
    cudaGetSymbolAddress((void**)&pM, g_M);
    cudaGetSymbolAddress((void**)&ph1, g_h1);
    cudaGetSymbolAddress((void**)&ph2, g_h2);

    size_t sm_k0 = sizeof(float) * (size_t)(160 * 129 + 160 + 8 * 400 + 400);
    size_t sm_l1 = layer_smem_bytes(128, 300, 4, 64);
    size_t sm_l2 = layer_smem_bytes(300, 100, 4, 64);
    size_t sm_fin = sizeof(float) * (size_t)(400 + 64 + 160 * 101 + 160 * 51 +
                                             64 * 101 + 16000 + 800 + 256 + 300 + 4 + 100);

    cudaFuncSetAttribute(knn0_kernel<8>, cudaFuncAttributeMaxDynamicSharedMemorySize, (int)sm_k0);
    cudaFuncSetAttribute((layer_kernel<128, 300, 4, true>), cudaFuncAttributeMaxDynamicSharedMemorySize, (int)sm_l1);
    cudaFuncSetAttribute((layer_kernel<300, 100, 4, true>), cudaFuncAttributeMaxDynamicSharedMemorySize, (int)sm_l2);
    cudaFuncSetAttribute(final_kernel, cudaFuncAttributeMaxDynamicSharedMemorySize, (int)sm_fin);

    zero_counts_kernel<<<5, 256>>>(pC);
    knn0_kernel<8><<<BATCH / 8, 256, sm_k0>>>(x, pC);
    build_M_kernel<<<1, 64>>>(pC, pM);
    layer_kernel<128, 300, 4, true><<<BATCH / 4, 256, sm_l1>>>(x, W1, b1, pM, ph1, pC + 400);
    build_M_kernel<<<1, 64>>>(pC, pM);  // no-op repeat guard (cheap, keeps graph shape stable)
    build_M_kernel<<<1, 64>>>(pC + 400, pM + 400);
    layer_kernel<300, 100, 4, true><<<BATCH / 4, 256, sm_l2>>>(ph1, W2, b2, pM + 400, ph2, pC + 800);
    build_M_kernel<<<1, 64>>>(pC + 800, pM + 800);
    final_kernel<<<BATCH / 8, 256, sm_fin>>>(ph2, W3, b3, pM + 800, W4, b4, W5, b5, out);
}

// round 4
// speedup vs baseline: 1.2614x; 1.2614x over previous
#include <cuda_runtime.h>
#include <math.h>

#define BATCH 16384
#define KNN 5

// ---------------- scratch (static device arrays; no allocation) ----------------
__device__ float g_h1[BATCH * 20 * 300];   // layer1 output
__device__ float g_h2[BATCH * 20 * 100];   // layer2 output
__device__ float g_C[3 * 400];             // kNN edge counts per layer
__device__ float g_M[3 * 400];             // aggregation matrices

// ---------------- tiny kernels ----------------
__global__ void zero_counts_kernel(float* C) {
    int t = blockIdx.x * blockDim.x + threadIdx.x;
    if (t < 1200) C[t] = 0.f;
}

__global__ void build_M_kernel(const float* __restrict__ C, float* __restrict__ M) {
    __shared__ float dinv[20];
    int t = threadIdx.x;
    if (t < 20) {
        float s = 1.f;
#pragma unroll
        for (int u = 0; u < 20; u++) s += C[t * 20 + u];
        dinv[t] = 1.f / sqrtf(s);
    }
    __syncthreads();
    for (int i = t; i < 400; i += blockDim.x) {
        int v = i / 20, u = i % 20;
        float m = dinv[v] * C[i] * dinv[u];
        if (v == u) m += dinv[v] * dinv[v];
        M[i] = m;
    }
}

// ---------------- block-local kNN + count accumulation ----------------
// sh: [NS*20][STRIDE] feature tile in smem. Emulates jax top_k(-d2, k+1)[1:]
// (self excluded; ties -> lower index, matched by strict < with ascending u).
template<int NS, int DIM, int STRIDE>
__device__ void knn_accumulate(const float* __restrict__ sh,
                               float* __restrict__ sdq, float* __restrict__ sd2,
                               float* __restrict__ sC, float* __restrict__ gC,
                               int tid) {
    constexpr int ROWS = NS * 20;
    for (int i = tid; i < 400; i += 256) sC[i] = 0.f;
    for (int t = tid; t < ROWS; t += 256) {
        const float* hp = sh + t * STRIDE;
        float s = 0.f;
        for (int d = 0; d < DIM; d++) { float h = hp[d]; s += h * h; }
        sdq[t] = s;
    }
    __syncthreads();
    for (int t = tid; t < NS * 190; t += 256) {
        int s = t / 190, rem = t % 190;
        int i = 0;
        while (rem >= 19 - i) { rem -= 19 - i; i++; }
        int j = i + 1 + rem;
        const float* ha = sh + (s * 20 + i) * STRIDE;
        const float* hb = sh + (s * 20 + j) * STRIDE;
        float dot = 0.f;
        for (int d = 0; d < DIM; d++) dot += ha[d] * hb[d];
        float d2 = sdq[s * 20 + i] + sdq[s * 20 + j] - 2.f * dot;
        sd2[s * 400 + i * 20 + j] = d2;
        sd2[s * 400 + j * 20 + i] = d2;
    }
    __syncthreads();
    for (int t = tid; t < ROWS; t += 256) {
        int s = t / 20, v = t % 20;
        const float* row = sd2 + s * 400 + v * 20;
        float bv[KNN]; int bi[KNN];
#pragma unroll
        for (int k = 0; k < KNN; k++) { bv[k] = 3.4e38f; bi[k] = 99; }
        for (int u = 0; u < 20; u++) {
            if (u == v) continue;
            float d = row[u];
            if (d < bv[KNN - 1]) {
                bv[KNN - 1] = d; bi[KNN - 1] = u;
#pragma unroll
                for (int k = KNN - 1; k > 0; k--) {
                    if (bv[k] < bv[k - 1]) {
                        float tv = bv[k]; bv[k] = bv[k - 1]; bv[k - 1] = tv;
                        int ti = bi[k]; bi[k] = bi[k - 1]; bi[k - 1] = ti;
                    }
                }
            }
        }
#pragma unroll
        for (int k = 0; k < KNN; k++)
            atomicAdd(&sC[bi[k] * 20 + v], 1.f);   // C[nbr][src]
    }
    __syncthreads();
    for (int i = tid; i < 400; i += 256) {
        float c = sC[i];
        if (c != 0.f) atomicAdd(&gC[i], c);
    }
}

// ---------------- kNN on raw x (layer-1 counts) ----------------
template<int NS>
__global__ __launch_bounds__(256) void knn0_kernel(const float* __restrict__ x,
                                                   float* __restrict__ gC) {
    constexpr int DIM = 128, DIMP = 129, ROWS = NS * 20;
    extern __shared__ float sm[];
    float* sh  = sm;
    float* sdq = sh + ROWS * DIMP;
    float* sd2 = sdq + ROWS;
    float* sC  = sd2 + NS * 400;
    int tid = threadIdx.x;
    size_t samp0 = (size_t)blockIdx.x * NS;
    const float* gx = x + samp0 * 20 * DIM;
    for (int idx = tid; idx < ROWS * DIM; idx += 256) {
        int r = idx / DIM, d = idx - r * DIM;
        sh[r * DIMP + d] = gx[idx];
    }
    __syncthreads();
    knn_accumulate<NS, DIM, DIMP>(sh, sdq, sd2, sC, gC, tid);
}

// ---------------- fused GCN layer ----------------
// AGG_BEFORE=true : h' = relu((M h) @ W^T + b)  (aggregation commutes with W)
// AGG_BEFORE=false: z = h @ W^T ; h' = relu(M z + b)
// Then kNN counts on h'.
template<int DIN, int DOUT, int NS, bool AGG_BEFORE>
__global__ __launch_bounds__(256) void layer_kernel(
    const float* __restrict__ hin, const float* __restrict__ W,
    const float* __restrict__ bias, const float* __restrict__ Mptr,
    float* __restrict__ hout, float* __restrict__ Cnext) {
    constexpr int HSTR  = DIN + 4;    // float4-aligned rows for h
    constexpr int WSTR  = DIN + 5;    // odd stride -> conflict-free strided-col w reads
    constexpr int DOUTP = DOUT | 1;   // odd stride for sz
    constexpr int ROWS  = NS * 20;
    constexpr int WCH   = 64;
    extern __shared__ float sm[];
    float* sM  = sm;                    // 400
    float* sb  = sM + 400;              // DOUT (mult of 4)
    float* sh  = sb + DOUT;             // ROWS*HSTR
    float* sz  = sh + ROWS * HSTR;      // ROWS*DOUTP
    float* sW  = sz + ROWS * DOUTP;     // WCH*WSTR
    float* sdq = sW + WCH * WSTR;       // ROWS
    float* sd2 = sdq + ROWS;            // NS*400
    float* sC  = sd2 + NS * 400;        // 400

    int tid = threadIdx.x;
    size_t samp0 = (size_t)blockIdx.x * NS;

    for (int i = tid; i < 400; i += 256) sM[i] = Mptr[i];
    for (int i = tid; i < DOUT; i += 256) sb[i] = bias[i];
    const float* gh = hin + samp0 * 20 * DIN;
    for (int idx = tid; idx < ROWS * DIN; idx += 256) {
        int r = idx / DIN, d = idx - r * DIN;
        sh[r * HSTR + d] = gh[idx];
    }
    __syncthreads();

    int lane = tid & 31, wid = tid >> 5;
    float Mr[20];
    {
        int v = lane < 20 ? lane : 0;
#pragma unroll
        for (int u = 0; u < 20; u++) Mr[u] = sM[v * 20 + u];
    }

    if (AGG_BEFORE) {
        // In-place g = M*h, column-group (float4) at a time. Lane v produces
        // row v of the sample; reads complete before the guarded write.
        constexpr int NGRP = NS * (DIN / 4);
        for (int g = wid; g < NGRP; g += 8) {
            int s = g / (DIN / 4), d4 = (g % (DIN / 4)) * 4;
            float* c0 = sh + (s * 20) * HSTR + d4;
            float4 a = make_float4(0.f, 0.f, 0.f, 0.f);
#pragma unroll
            for (int u = 0; u < 20; u++) {
                float4 z4 = *reinterpret_cast<const float4*>(c0 + u * HSTR);
                float m = Mr[u];
                a.x += m * z4.x; a.y += m * z4.y; a.z += m * z4.z; a.w += m * z4.w;
            }
            __syncwarp();
            if (lane < 20) *reinterpret_cast<float4*>(c0 + lane * HSTR) = a;
            __syncwarp();
        }
        __syncthreads();
    }

    // GEMM: sz[r][o] = sum_d sh[r][d] * W[o][d]
    // Thread (ty,tx): rows ty*5..+5, cols {cb+tx, cb+tx+16, cb+tx+32, cb+tx+48}.
    int ty = tid >> 4, tx = tid & 15;
    for (int cb = 0; cb < DOUT; cb += WCH) {
        __syncthreads();
        for (int idx = tid; idx < WCH * DIN; idx += 256) {
            int c = idx / DIN, d = idx - c * DIN;
            int gc = cb + c;
            sW[c * WSTR + d] = (gc < DOUT) ? W[(size_t)gc * DIN + d] : 0.f;
        }
        __syncthreads();
        float acc[5][4];
#pragma unroll
        for (int i = 0; i < 5; i++)
#pragma unroll
            for (int k = 0; k < 4; k++) acc[i][k] = 0.f;
        const float* shp = sh + (ty * 5) * HSTR;
        const float* sw0 = sW + tx * WSTR;
        for (int d = 0; d < DIN; d += 4) {
            float4 A[5];
#pragma unroll
            for (int i = 0; i < 5; i++)
                A[i] = *reinterpret_cast<const float4*>(shp + i * HSTR + d);
#pragma unroll
            for (int k = 0; k < 4; k++) {
                const float* wp = sw0 + k * 16 * WSTR + d;
                float w0 = wp[0], w1 = wp[1], w2 = wp[2], w3 = wp[3];
#pragma unroll
                for (int i = 0; i < 5; i++) {
                    acc[i][k] += A[i].x * w0;
                    acc[i][k] += A[i].y * w1;
                    acc[i][k] += A[i].z * w2;
                    acc[i][k] += A[i].w * w3;
                }
            }
        }
#pragma unroll
        for (int k = 0; k < 4; k++) {
            int gc = cb + tx + k * 16;
            if (gc < DOUT) {
#pragma unroll
                for (int i = 0; i < 5; i++) {
                    float v = acc[i][k];
                    if (AGG_BEFORE) v = fmaxf(v + sb[gc], 0.f);
                    sz[(ty * 5 + i) * DOUTP + gc] = v;
                }
            }
        }
    }
    __syncthreads();

    if (!AGG_BEFORE) {
        // in-place h' = relu(M z + b): lane v computes row v of each column
        for (int col = wid; col < NS * DOUT; col += 8) {
            int s = col / DOUT, o = col - s * DOUT;
            float* zc = sz + (s * 20) * DOUTP + o;
            float a = 0.f;
#pragma unroll
            for (int u = 0; u < 20; u++) a += Mr[u] * zc[u * DOUTP];
            float h = fmaxf(a + sb[o], 0.f);
            __syncwarp();
            if (lane < 20) zc[lane * DOUTP] = h;
            __syncwarp();
        }
        __syncthreads();
    }

    float* go = hout + samp0 * 20 * DOUT;
    for (int idx = tid; idx < ROWS * DOUT; idx += 256) {
        int r = idx / DOUT, o = idx - r * DOUT;
        go[idx] = sz[r * DOUTP + o];
    }

    knn_accumulate<NS, DOUT, DOUTP>(sz, sdq, sd2, sC, Cnext, tid);
}

// ---------------- layer3 + flatten + FC head + softmax ----------------
#define W4STR 1005   // odd-ish stride (mod 32 = 13) -> conflict-free jl-strided reads
__global__ __launch_bounds__(256) void final_kernel(
    const float* __restrict__ hin, const float* __restrict__ W3, const float* __restrict__ b3,
    const float* __restrict__ Mptr, const float* __restrict__ W4, const float* __restrict__ b4,
    const float* __restrict__ W5, const float* __restrict__ b5, float* __restrict__ out) {
    constexpr int DIN = 100, DINP = 101, DOUT = 50, DOUTP = 51;
    constexpr int NS = 8, ROWS = 160, WCH = 64;
    extern __shared__ float sm[];
    float* sM  = sm;                 // 400
    float* sb3 = sM + 400;           // 64 (padded)
    float* sh  = sb3 + 64;           // 160*101
    float* sz  = sh + ROWS * DINP;   // 160*51
    float* sW  = sz + ROWS * DOUTP;  // 64*101
    float* sW4 = sW + WCH * DINP;    // 16*W4STR
    float* sh4 = sW4 + 16 * W4STR;   // 8*100
    float* ph  = sh4 + NS * 100;     // 256
    float* sW5 = ph + 256;           // 300
    float* sb5 = sW5 + 300;          // 4
    float* sb4 = sb5 + 4;            // 100

    int tid = threadIdx.x;
    size_t samp0 = (size_t)blockIdx.x * NS;

    for (int i = tid; i < 400; i += 256) sM[i] = Mptr[i];
    for (int i = tid; i < DOUT; i += 256) sb3[i] = b3[i];
    for (int i = tid; i < 300; i += 256) sW5[i] = W5[i];
    for (int i = tid; i < 100; i += 256) sb4[i] = b4[i];
    if (tid < 3) sb5[tid] = b5[tid];
    const float* gh = hin + samp0 * 20 * DIN;
    for (int idx = tid; idx < ROWS * DIN; idx += 256) {
        int r = idx / DIN, d = idx - r * DIN;
        sh[r * DINP + d] = gh[idx];
    }
    // W3 chunk (single, zero-padded to WCH)
    for (int idx = tid; idx < WCH * DIN; idx += 256) {
        int c = idx / DIN, d = idx - c * DIN;
        sW[c * DINP + d] = (c < DOUT) ? W3[c * DIN + d] : 0.f;
    }
    __syncthreads();

    int lane = tid & 31, wid = tid >> 5;
    float Mr[20];
    {
        int v = lane < 20 ? lane : 0;
#pragma unroll
        for (int u = 0; u < 20; u++) Mr[u] = sM[v * 20 + u];
    }

    // GEMM z = h @ W3^T : 160 rows, 10 rows per ty, strided cols
    int ty = tid >> 4, tx = tid & 15;
    {
        float acc[10][4];
#pragma unroll
        for (int i = 0; i < 10; i++)
#pragma unroll
            for (int k = 0; k < 4; k++) acc[i][k] = 0.f;
        const float* shp = sh + (ty * 10) * DINP;
        const float* sw0 = sW + tx * DINP;
        for (int d = 0; d < DIN; d++) {
            float a[10];
#pragma unroll
            for (int i = 0; i < 10; i++) a[i] = shp[i * DINP + d];
#pragma unroll
            for (int k = 0; k < 4; k++) {
                float w = sw0[k * 16 * DINP + d];
#pragma unroll
                for (int i = 0; i < 10; i++) acc[i][k] += a[i] * w;
            }
        }
#pragma unroll
        for (int k = 0; k < 4; k++) {
            int gc = tx + k * 16;
            if (gc < DOUT) {
#pragma unroll
                for (int i = 0; i < 10; i++)
                    sz[(ty * 10 + i) * DOUTP + gc] = acc[i][k];
            }
        }
    }
    __syncthreads();

    // h3 = relu(M z + b3) in place
    for (int col = wid; col < NS * DOUT; col += 8) {
        int s = col / DOUT, o = col - s * DOUT;
        float* zc = sz + (s * 20) * DOUTP + o;
        float a = 0.f;
#pragma unroll
        for (int u = 0; u < 20; u++) a += Mr[u] * zc[u * DOUTP];
        float h = fmaxf(a + sb3[o], 0.f);
        __syncwarp();
        if (lane < 20) zc[lane * DOUTP] = h;
        __syncwarp();
    }
    __syncthreads();

    // head: h4 = relu(flat @ W4^T + b4), W4 streamed in 16-row smem chunks.
    // 100 rows = 6 full chunks of 16 + partial 4; guarded loads/stores.
    for (int jc = 0; jc < 100; jc += 16) {
        __syncthreads();
        for (int idx = tid; idx < 16000; idx += 256) {
            int rloc = idx / 1000, cloc = idx - rloc * 1000;
            int r = jc + rloc;
            sW4[rloc * W4STR + cloc] = (r < 100) ? W4[(size_t)r * 1000 + cloc] : 0.f;
        }
        __syncthreads();
        int task = tid & 127;   // (s, jl) pair
        int half = tid >> 7;    // split n-dim in two
        int s = task >> 4, jl = task & 15;
        const float* zrow = sz + (s * 20) * DOUTP;
        const float* wrow = sW4 + jl * W4STR;
        float p = 0.f;
        int v0 = half * 10;
        for (int v = v0; v < v0 + 10; v++) {
            const float* zp = zrow + v * DOUTP;
            const float* wp = wrow + v * 50;
#pragma unroll 10
            for (int f = 0; f < 50; f++) p += zp[f] * wp[f];
        }
        ph[tid] = p;
        __syncthreads();
        if (tid < 128) {
            int s2 = tid >> 4, jl2 = tid & 15;
            if (jc + jl2 < 100) {
                float hv = ph[tid] + ph[tid + 128] + sb4[jc + jl2];
                sh4[s2 * 100 + jc + jl2] = fmaxf(hv, 0.f);
            }
        }
    }
    __syncthreads();

    // logits + softmax
    if (tid < NS) {
        const float* hp = sh4 + tid * 100;
        float l[3];
#pragma unroll
        for (int c = 0; c < 3; c++) {
            float a = sb5[c];
            for (int j = 0; j < 100; j++) a += hp[j] * sW5[c * 100 + j];
            l[c] = a;
        }
        float mx = fmaxf(l[0], fmaxf(l[1], l[2]));
        float e0 = expf(l[0] - mx), e1 = expf(l[1] - mx), e2 = expf(l[2] - mx);
        float inv = 1.f / (e0 + e1 + e2);
        size_t ob = (samp0 + (size_t)tid) * 3;
        out[ob + 0] = e0 * inv;
        out[ob + 1] = e1 * inv;
        out[ob + 2] = e2 * inv;
    }
}

// ---------------- host ----------------
static size_t layer_smem_bytes(int DIN, int DOUT, int NS, int WCH) {
    int HSTR = DIN + 4, WSTR = DIN + 5, DOUTP = DOUT | 1, ROWS = NS * 20;
    return sizeof(float) * (size_t)(400 + DOUT + ROWS * HSTR + ROWS * DOUTP +
                                    WCH * WSTR + ROWS + NS * 400 + 400);
}

extern "C" void kernel_launch(void* const* d_in, const int* in_sizes, int n_in,
                              void* d_out, int out_size) {
    // ---- robust, size-driven input resolution ----
    const float *x = 0, *W1 = 0, *b1 = 0, *W2 = 0, *b2 = 0, *W3 = 0, *b3 = 0,
                *W4 = 0, *b4 = 0, *W5 = 0, *b5 = 0;
    int idx_x = -1;
    for (int i = 0; i < n_in; i++) if (in_sizes[i] == 41943040) { idx_x = i; break; }
    if (idx_x == 0 || idx_x < 0) {
        // insertion order: x, W1, b1, W2, b2, W3, b3, W4, b4, W5, b5
        x  = (const float*)d_in[0];
        W1 = (const float*)d_in[1];  b1 = (const float*)d_in[2];
        W2 = (const float*)d_in[3];  b2 = (const float*)d_in[4];
        W3 = (const float*)d_in[5];  b3 = (const float*)d_in[6];
        W4 = (const float*)d_in[7];  b4 = (const float*)d_in[8];
        W5 = (const float*)d_in[9];  b5 = (const float*)d_in[10];
    } else {
        int i300_a = -1, i300_b = -1, i100_a = -1, i100_b = -1;
        for (int i = 0; i < n_in; i++) {
            int s = in_sizes[i];
            if (s == 38400)  W1 = (const float*)d_in[i];
            else if (s == 30000) W2 = (const float*)d_in[i];
            else if (s == 5000)  W3 = (const float*)d_in[i];
            else if (s == 100000) W4 = (const float*)d_in[i];
            else if (s == 50)    b3 = (const float*)d_in[i];
            else if (s == 3)     b5 = (const float*)d_in[i];
            else if (s == 41943040) x = (const float*)d_in[i];
            else if (s == 300) { if (i300_a < 0) i300_a = i; else i300_b = i; }
            else if (s == 100) { if (i100_a < 0) i100_a = i; else i100_b = i; }
        }
        W5 = (const float*)d_in[i300_a];  b1 = (const float*)d_in[i300_b];
        b2 = (const float*)d_in[i100_a];  b4 = (const float*)d_in[i100_b];
    }
    float* out = (float*)d_out;

    float *pC = nullptr, *pM = nullptr, *ph1 = nullptr, *ph2 = nullptr;
    cudaGetSymbolAddress((void**)&pC, g_C);
    cudaGetSymbolAddress((void**)&pM, g_M);
    cudaGetSymbolAddress((void**)&ph1, g_h1);
    cudaGetSymbolAddress((void**)&ph2, g_h2);

    size_t sm_k0 = sizeof(float) * (size_t)(160 * 129 + 160 + 8 * 400 + 400);
    size_t sm_l1 = layer_smem_bytes(128, 300, 4, 64);
    size_t sm_l2 = layer_smem_bytes(300, 100, 4, 64);
    size_t sm_fin = sizeof(float) * (size_t)(400 + 64 + 160 * 101 + 160 * 51 +
                                             64 * 101 + 16 * W4STR + 800 + 256 + 300 + 4 + 100);

    cudaFuncSetAttribute(knn0_kernel<8>, cudaFuncAttributeMaxDynamicSharedMemorySize, (int)sm_k0);
    cudaFuncSetAttribute((layer_kernel<128, 300, 4, true>), cudaFuncAttributeMaxDynamicSharedMemorySize, (int)sm_l1);
    cudaFuncSetAttribute((layer_kernel<300, 100, 4, false>), cudaFuncAttributeMaxDynamicSharedMemorySize, (int)sm_l2);
    cudaFuncSetAttribute(final_kernel, cudaFuncAttributeMaxDynamicSharedMemorySize, (int)sm_fin);

    zero_counts_kernel<<<5, 256>>>(pC);
    knn0_kernel<8><<<BATCH / 8, 256, sm_k0>>>(x, pC);
    build_M_kernel<<<1, 64>>>(pC, pM);
    layer_kernel<128, 300, 4, true><<<BATCH / 4, 256, sm_l1>>>(x, W1, b1, pM, ph1, pC + 400);
    build_M_kernel<<<1, 64>>>(pC + 400, pM + 400);
    layer_kernel<300, 100, 4, false><<<BATCH / 4, 256, sm_l2>>>(ph1, W2, b2, pM + 400, ph2, pC + 800);
    build_M_kernel<<<1, 64>>>(pC + 800, pM + 800);
    final_kernel<<<BATCH / 8, 256, sm_fin>>>(ph2, W3, b3, pM + 800, W4, b4, W5, b5, out);
}